// round 5
// baseline (speedup 1.0000x reference)
#include <cuda_runtime.h>
#include <cstdint>

#define Bc   256
#define Nc   1024
#define Dc   128
#define QSc  256
#define CIN  384     // [q(128) | r(128) | h-dup(128)]
#define HIDc 256
#define NTHR 512
#define TROWS 64
#define NTILES 16
#define TILE_B (TROWS * Dc * 4)   // 32768 bytes per tile

// Packed weights: g_W4[c*128 + d] = {W_i, W_f, W_g, W_o} for input-col c, dim d.
__device__ float4 g_W4[CIN * Dc];
__device__ float4 g_bias4[Dc];
__device__ float  g_WlinT[QSc * HIDc];

// ---- dynamic SMEM layout (bytes) ----
// xs: 6 tile buffers (3 per batch)  [bt][buf]
#define OFF_XS   0
#define SZ_XS    (6 * TILE_B)                 // 196608
// U: union { gp: float4[2][4][128] (16384) ; red: float[2][16][160] (20480) }
//    gp lives gates->LSTM; red lives post-attention->reduction. Disjoint.
#define OFF_U    (OFF_XS + SZ_XS)
#define SZ_U     20480
#define OFF_LRED (OFF_U + SZ_U)               // float[2][16]
#define SZ_LRED  128
#define OFF_SQ   (OFF_LRED + SZ_LRED)         // float[2][384]
#define SZ_SQ    (2 * 384 * 4)
#define SMEM_TOTAL (OFF_SQ + SZ_SQ)           // 220288 B ≈ 215.1 KB

__global__ void prep_kernel(const float* __restrict__ W_ih,
                            const float* __restrict__ W_hh,
                            const float* __restrict__ b_ih,
                            const float* __restrict__ b_hh,
                            const float* __restrict__ W_lin) {
    int tid = blockIdx.x * blockDim.x + threadIdx.x;
    int nt  = gridDim.x * blockDim.x;
    for (int idx = tid; idx < CIN * Dc; idx += nt) {
        int c = idx >> 7, d = idx & 127;
        float4 w;
        if (c < QSc) {
            w.x = W_ih[(d         ) * QSc + c];
            w.y = W_ih[(d + Dc    ) * QSc + c];
            w.z = W_ih[(d + 2*Dc  ) * QSc + c];
            w.w = W_ih[(d + 3*Dc  ) * QSc + c];
        } else {
            int cc = c - QSc;
            w.x = W_hh[(d         ) * Dc + cc];
            w.y = W_hh[(d + Dc    ) * Dc + cc];
            w.z = W_hh[(d + 2*Dc  ) * Dc + cc];
            w.w = W_hh[(d + 3*Dc  ) * Dc + cc];
        }
        g_W4[idx] = w;
    }
    for (int d = tid; d < Dc; d += nt) {
        float4 bb;
        bb.x = b_ih[d       ] + b_hh[d       ];
        bb.y = b_ih[d +   Dc] + b_hh[d +   Dc];
        bb.z = b_ih[d + 2*Dc] + b_hh[d + 2*Dc];
        bb.w = b_ih[d + 3*Dc] + b_hh[d + 3*Dc];
        g_bias4[d] = bb;
    }
    for (int idx = tid; idx < QSc * HIDc; idx += nt) {
        int c = idx >> 8, o = idx & 255;
        g_WlinT[idx] = W_lin[o * QSc + c];
    }
}

__device__ __forceinline__ float sigf(float x) {
    return __fdividef(1.0f, 1.0f + __expf(-x));
}
__device__ __forceinline__ float tanh_acc(float x) {
    return __fdividef(2.0f, 1.0f + __expf(-2.0f * x)) - 1.0f;
}
__device__ __forceinline__ void cp16(void* dst, const void* src) {
    uint32_t d = (uint32_t)__cvta_generic_to_shared(dst);
    asm volatile("cp.async.cg.shared.global [%0], [%1], 16;" :: "r"(d), "l"(src));
}
#define CP_COMMIT() asm volatile("cp.async.commit_group;")
#define CP_WAIT1()  asm volatile("cp.async.wait_group 1;")
#define CP_WAIT0()  asm volatile("cp.async.wait_group 0;")

__global__ void __launch_bounds__(NTHR, 1)
s2s_kernel(const float* __restrict__ x,
           const float* __restrict__ b_lin,
           float* __restrict__ out) {
    extern __shared__ char smem[];
    char*   xs   = smem + OFF_XS;
    float4* gp   = (float4*)(smem + OFF_U);      // gates->LSTM lifetime
    float*  red  = (float*)(smem + OFF_U);       // post-attention lifetime
    float*  lred = (float*)(smem + OFF_LRED);
    float*  sq   = (float*)(smem + OFF_SQ);

    const int tid = threadIdx.x;
    const int d   = tid & 127;   // gate dim
    const int p   = tid >> 7;    // gate c-quarter
    const int q   = tid >> 3;    // attention row-in-tile (0..63)
    const int j   = tid & 7;     // attention 16-dim chunk (0..7)
    const int wrp = tid >> 5;    // 0..15
    const int lane = tid & 31;

    if (tid < CIN)       sq[tid] = 0.0f;
    if (tid < CIN) sq[384 + tid] = 0.0f;
    float c_state = 0.0f;

    const float* xa  = x + (size_t)(blockIdx.x * 2    ) * Nc * Dc;
    const float* xbp = x + (size_t)(blockIdx.x * 2 + 1) * Nc * Dc;

    // swizzled SMEM byte offsets for attention LDS.128 reads (row q, chunk j)
    int roff[4];
    #pragma unroll
    for (int i = 0; i < 4; i++) {
        int gi = 4 * j + i;
        int V  = ((q & 1) << 2) | (gi >> 3);
        roff[i] = q * 512 + ((gi >> 3) << 7) + (((gi & 7) ^ V) << 4);
    }
    // cp.async granule offsets
    int soff[4], doff[4];
    #pragma unroll
    for (int k = 0; k < 4; k++) {
        int G = tid + NTHR * k;
        int rr = G >> 5, g = G & 31;
        int V = ((rr & 1) << 2) | (g >> 3);
        soff[k] = rr * Dc + g * 4;
        doff[k] = rr * 512 + ((g >> 3) << 7) + (((g & 7) ^ V) << 4);
    }

    const float4* Wp = g_W4 + (size_t)p * 96 * Dc + d;
    const float4  bias = g_bias4[d];

    __syncthreads();

    for (int t = 0; t < Nc; t++) {
        // ---- prologue: tiles 0,1 of both batches (one commit per tile-pair) ----
        #pragma unroll
        for (int tt = 0; tt < 2; tt++) {
            const float* sa = xa  + (size_t)tt * TROWS * Dc;
            const float* sb = xbp + (size_t)tt * TROWS * Dc;
            char* da = xs + (0 * 3 + tt) * TILE_B;
            char* db = xs + (1 * 3 + tt) * TILE_B;
            #pragma unroll
            for (int k = 0; k < 4; k++) cp16(da + doff[k], sa + soff[k]);
            #pragma unroll
            for (int k = 0; k < 4; k++) cp16(db + doff[k], sb + soff[k]);
            CP_COMMIT();
        }

        // ---- gates: shared-weight GEMV for BOTH batches ----
        float4 aa = make_float4(0.f,0.f,0.f,0.f);
        float4 ab = make_float4(0.f,0.f,0.f,0.f);
        const float* qa_base = sq +       p * 96;
        const float* qb_base = sq + 384 + p * 96;
        #pragma unroll 4
        for (int c4 = 0; c4 < 96; c4 += 4) {
            float4 qa = *(const float4*)(qa_base + c4);
            float4 qb = *(const float4*)(qb_base + c4);
            float4 w0 = Wp[(c4 + 0) * Dc];
            float4 w1 = Wp[(c4 + 1) * Dc];
            float4 w2 = Wp[(c4 + 2) * Dc];
            float4 w3 = Wp[(c4 + 3) * Dc];
            aa.x=fmaf(qa.x,w0.x,aa.x); aa.y=fmaf(qa.x,w0.y,aa.y); aa.z=fmaf(qa.x,w0.z,aa.z); aa.w=fmaf(qa.x,w0.w,aa.w);
            ab.x=fmaf(qb.x,w0.x,ab.x); ab.y=fmaf(qb.x,w0.y,ab.y); ab.z=fmaf(qb.x,w0.z,ab.z); ab.w=fmaf(qb.x,w0.w,ab.w);
            aa.x=fmaf(qa.y,w1.x,aa.x); aa.y=fmaf(qa.y,w1.y,aa.y); aa.z=fmaf(qa.y,w1.z,aa.z); aa.w=fmaf(qa.y,w1.w,aa.w);
            ab.x=fmaf(qb.y,w1.x,ab.x); ab.y=fmaf(qb.y,w1.y,ab.y); ab.z=fmaf(qb.y,w1.z,ab.z); ab.w=fmaf(qb.y,w1.w,ab.w);
            aa.x=fmaf(qa.z,w2.x,aa.x); aa.y=fmaf(qa.z,w2.y,aa.y); aa.z=fmaf(qa.z,w2.z,aa.z); aa.w=fmaf(qa.z,w2.w,aa.w);
            ab.x=fmaf(qb.z,w2.x,ab.x); ab.y=fmaf(qb.z,w2.y,ab.y); ab.z=fmaf(qb.z,w2.z,ab.z); ab.w=fmaf(qb.z,w2.w,ab.w);
            aa.x=fmaf(qa.w,w3.x,aa.x); aa.y=fmaf(qa.w,w3.y,aa.y); aa.z=fmaf(qa.w,w3.z,aa.z); aa.w=fmaf(qa.w,w3.w,aa.w);
            ab.x=fmaf(qb.w,w3.x,ab.x); ab.y=fmaf(qb.w,w3.y,ab.y); ab.z=fmaf(qb.w,w3.z,ab.z); ab.w=fmaf(qb.w,w3.w,ab.w);
        }
        gp[(0 * 4 + p) * Dc + d] = aa;
        gp[(1 * 4 + p) * Dc + d] = ab;
        __syncthreads();

        // ---- LSTM cell (threads 0..255) ----
        if (tid < 256) {
            int bt = tid >> 7;
            float4 s0 = gp[(bt*4+0)*Dc + d];
            float4 s1 = gp[(bt*4+1)*Dc + d];
            float4 s2 = gp[(bt*4+2)*Dc + d];
            float4 s3 = gp[(bt*4+3)*Dc + d];
            float gi = s0.x+s1.x+s2.x+s3.x + bias.x;
            float gf = s0.y+s1.y+s2.y+s3.y + bias.y;
            float gg = s0.z+s1.z+s2.z+s3.z + bias.z;
            float go = s0.w+s1.w+s2.w+s3.w + bias.w;
            c_state = fmaf(sigf(gf), c_state, sigf(gi) * tanh_acc(gg));
            float h = sigf(go) * tanh_acc(c_state);
            sq[bt*384 + d]       = h;
            sq[bt*384 + 256 + d] = h;
        }

        // ---- attention: 16 tiles, ONE sync per tile (3 bufs/batch) ----
        float4 qr[2][4];
        float rp[2][16];
        float lac[2] = {0.0f, 0.0f};
        #pragma unroll
        for (int bt = 0; bt < 2; bt++)
            #pragma unroll
            for (int k = 0; k < 16; k++) rp[bt][k] = 0.0f;

        for (int tt = 0; tt < NTILES; tt++) {
            if (tt < NTILES - 1) { CP_WAIT1(); } else { CP_WAIT0(); }
            __syncthreads();   // tile tt visible to all; doubles as LSTM sync at tt=0

            if (tt == 0) {     // q just became visible
                #pragma unroll
                for (int bt = 0; bt < 2; bt++)
                    #pragma unroll
                    for (int i = 0; i < 4; i++)
                        qr[bt][i] = *(const float4*)(sq + bt*384 + 16*j + 4*i);
            }
            // prefetch tile tt+2 into buf (tt+2)%3 — its last readers (tile tt-1)
            // all passed the barrier above, so no WAR hazard.
            if (tt + 2 < NTILES) {
                int buf = (tt + 2) % 3;
                const float* sa = xa  + (size_t)(tt+2) * TROWS * Dc;
                const float* sb = xbp + (size_t)(tt+2) * TROWS * Dc;
                char* da = xs + (0 * 3 + buf) * TILE_B;
                char* db = xs + (1 * 3 + buf) * TILE_B;
                #pragma unroll
                for (int k = 0; k < 4; k++) cp16(da + doff[k], sa + soff[k]);
                #pragma unroll
                for (int k = 0; k < 4; k++) cp16(db + doff[k], sb + soff[k]);
                CP_COMMIT();
            }

            int buf = tt % 3;
            #pragma unroll
            for (int bt = 0; bt < 2; bt++) {
                const char* tb = xs + (bt * 3 + buf) * TILE_B;
                float4 xr[4];
                float e = 0.0f;
                #pragma unroll
                for (int i = 0; i < 4; i++) {
                    xr[i] = *(const float4*)(tb + roff[i]);
                    e = fmaf(xr[i].x, qr[bt][i].x, e);
                    e = fmaf(xr[i].y, qr[bt][i].y, e);
                    e = fmaf(xr[i].z, qr[bt][i].z, e);
                    e = fmaf(xr[i].w, qr[bt][i].w, e);
                }
                e += __shfl_xor_sync(0xffffffffu, e, 1);
                e += __shfl_xor_sync(0xffffffffu, e, 2);
                e += __shfl_xor_sync(0xffffffffu, e, 4);
                float pw = __expf(e - 40.0f);   // |e| << 40 by construction
                lac[bt] += pw;
                #pragma unroll
                for (int i = 0; i < 4; i++) {
                    rp[bt][4*i+0] = fmaf(pw, xr[i].x, rp[bt][4*i+0]);
                    rp[bt][4*i+1] = fmaf(pw, xr[i].y, rp[bt][4*i+1]);
                    rp[bt][4*i+2] = fmaf(pw, xr[i].z, rp[bt][4*i+2]);
                    rp[bt][4*i+3] = fmaf(pw, xr[i].w, rp[bt][4*i+3]);
                }
            }
        }
        __syncthreads();   // all reads of last tiles done; U region switches gp->red

        // ---- warp pre-reduction: collapse the 4 rows per warp (xor 8, 16) ----
        #pragma unroll
        for (int bt = 0; bt < 2; bt++) {
            #pragma unroll
            for (int k = 0; k < 16; k++) {
                float v = rp[bt][k];
                v += __shfl_xor_sync(0xffffffffu, v, 8);
                v += __shfl_xor_sync(0xffffffffu, v, 16);
                rp[bt][k] = v;
            }
            float lv = lac[bt];
            lv += __shfl_xor_sync(0xffffffffu, lv, 8);
            lv += __shfl_xor_sync(0xffffffffu, lv, 16);
            // note: all 8 lanes of a j-group carry identical p, so lane0's lv
            // counts each of the warp's rows exactly once per j -> use j==0 lane
            if (lane == 0) lred[bt * 16 + wrp] = lv;
            if (lane < 8) {
                // red[bt][wrp][lane*20 + k] (stride 20 -> conflict-free STS.128)
                float* rw = red + (bt * 16 + wrp) * 160 + lane * 20;
                #pragma unroll
                for (int i = 0; i < 4; i++)
                    *(float4*)(rw + 4 * i) = make_float4(rp[bt][4*i], rp[bt][4*i+1],
                                                         rp[bt][4*i+2], rp[bt][4*i+3]);
            }
        }
        __syncthreads();

        // ---- final reduction: threads 0..255, dim d, batch bt ----
        if (tid < 256) {
            int bt = tid >> 7;
            int jj = d >> 4, kk = d & 15;
            float rsum = 0.0f, L = 0.0f;
            #pragma unroll
            for (int w = 0; w < 16; w++) {
                rsum += red[(bt * 16 + w) * 160 + jj * 20 + kk];
                L    += lred[bt * 16 + w];
            }
            sq[bt*384 + Dc + d] = __fdividef(rsum, L);
        }
        __syncthreads();
    }

    // ---- epilogue: out = q_star @ W_lin^T + b_lin ----
    {
        int bt = tid >> 8;
        int o  = tid & 255;
        float acc = b_lin[o];
        #pragma unroll 8
        for (int c = 0; c < QSc; c++)
            acc = fmaf(sq[bt*384 + c], g_WlinT[c * HIDc + o], acc);
        out[(size_t)(blockIdx.x * 2 + bt) * HIDc + o] = acc;
    }
}

extern "C" void kernel_launch(void* const* d_in, const int* in_sizes, int n_in,
                              void* d_out, int out_size) {
    const float* x     = (const float*)d_in[0];
    const float* W_ih  = (const float*)d_in[1];
    const float* W_hh  = (const float*)d_in[2];
    const float* b_ih  = (const float*)d_in[3];
    const float* b_hh  = (const float*)d_in[4];
    const float* W_lin = (const float*)d_in[5];
    const float* b_lin = (const float*)d_in[6];
    float* out = (float*)d_out;

    cudaFuncSetAttribute(s2s_kernel, cudaFuncAttributeMaxDynamicSharedMemorySize,
                         SMEM_TOTAL);
    prep_kernel<<<256, 256>>>(W_ih, W_hh, b_ih, b_hh, W_lin);
    s2s_kernel<<<Bc / 2, NTHR, SMEM_TOTAL>>>(x, b_lin, out);
}